// round 4
// baseline (speedup 1.0000x reference)
#include <cuda_runtime.h>
#include <cuda_bf16.h>

// Problem constants (fixed-shape problem)
#define NPTS   400000
#define CIN    32
#define COUT   32
#define KTAPS  27

#define BLOCK1 256          // 8 warps
#define WARPS1 8
#define PW     16           // points per warp
#define PTSBLK (WARPS1*PW)  // 128 points per block
#define NBLK1  (NPTS/PTSBLK) // 3125 exactly (400000 = 128*3125)

#define TOTAL4 (NPTS*COUT/4) // 3,200,000 float4 elements for epilogue
#define NBLK3  (TOTAL4/256)  // 12500

// Scratch (static device memory — no allocations)
__device__ float g_conv[(size_t)NPTS * COUT];     // 51.2 MB conv output
__device__ float g_part[(size_t)NBLK1 * 64];      // per-block sum/sumsq
__device__ float g_coef[64];                      // scale[32], shift[32]
__device__ int   g_maskmode;                      // 0 = uint8 mask, 1 = int32 mask

// ---------------------------------------------------------------------------
// K0: detect the storage width of nbr_mask.
// View buffer as uint32. If mask is int32 {0,1}, all words <= 1.
// If mask is packed uint8 bools (~12% density), words > 1 appear immediately.
// ---------------------------------------------------------------------------
__global__ void detect_mask_kernel(const unsigned int* __restrict__ m)
{
    __shared__ int found;
    if (threadIdx.x == 0) found = 0;
    __syncthreads();
    int f = 0;
    for (int i = threadIdx.x; i < 4096; i += blockDim.x)
        if (m[i] > 1u) f = 1;
    if (f) atomicOr(&found, 1);
    __syncthreads();
    if (threadIdx.x == 0) g_maskmode = found ? 0 : 1;
}

// ---------------------------------------------------------------------------
// K1: gather-conv with mask skipping + per-block partial sums
// Warp layout: lane = c_out; each warp owns 16 consecutive points.
// Per k: weights staged block-wide into smem (double buffered), pulled into
// 32 regs per lane; valid taps found via ballot (warp-uniform, no divergence);
// gathered feature row staged via smem and broadcast with LDS.128.
// ---------------------------------------------------------------------------
__global__ __launch_bounds__(BLOCK1)
void conv_kernel(const float* __restrict__ feat,
                 const float* __restrict__ wglob,
                 const int*   __restrict__ nidx,
                 const unsigned char* __restrict__ nmask8,
                 const int*   __restrict__ nmask32,
                 float* __restrict__ convout,
                 float* __restrict__ partials)
{
    __shared__ float ws[2][CIN * COUT];              // 2 x 4 KB weight double buffer
    __shared__ __align__(16) float fs[WARPS1][CIN];  // per-warp gathered feature row
    __shared__ float red[2][WARPS1][COUT];

    const int tid  = threadIdx.x;
    const int wid  = tid >> 5;
    const int lane = tid & 31;
    const int n0   = blockIdx.x * PTSBLK + wid * PW;   // warp's first point
    const int maskmode = g_maskmode;

    float acc[PW];
#pragma unroll
    for (int p = 0; p < PW; p++) acc[p] = 0.0f;

    // preload k=0 weights
    for (int i = tid; i < CIN * COUT; i += BLOCK1) ws[0][i] = wglob[i];

    for (int k = 0; k < KTAPS; k++) {
        __syncthreads();   // staged weights for this k are visible
        const int buf = k & 1;

        // pull my weight column (all ci for my c_out) into registers
        float wr[CIN];
#pragma unroll
        for (int ci = 0; ci < CIN; ci++) wr[ci] = ws[buf][ci * COUT + lane];

        // prefetch next k's weights into the other buffer (no hazard: the
        // other buffer's last reads happened before the barrier above)
        if (k + 1 < KTAPS) {
            const float* src = wglob + (k + 1) * (CIN * COUT);
            for (int i = tid; i < CIN * COUT; i += BLOCK1) ws[buf ^ 1][i] = src[i];
        }

        // per-warp neighbor idx/mask for this k (lanes 0..15 hold the 16 points)
        int  idxv = 0;
        bool mv   = false;
        if (lane < PW) {
            const size_t j = (size_t)k * NPTS + (n0 + lane);
            mv   = maskmode ? (nmask32[j] != 0) : (nmask8[j] != 0);
            idxv = nidx[j];
        }
        const unsigned vm = __ballot_sync(0xffffffffu, mv);

#pragma unroll
        for (int p = 0; p < PW; p++) {
            if (vm & (1u << p)) {                   // warp-uniform branch
                const int gi = __shfl_sync(0xffffffffu, idxv, p);
                const float fv = feat[(size_t)gi * CIN + lane];  // coalesced 128B gather
                fs[wid][lane] = fv;
                __syncwarp();
                const float4* fq = (const float4*)fs[wid];
#pragma unroll
                for (int j = 0; j < 8; j++) {
                    const float4 q = fq[j];
                    acc[p] = fmaf(q.x, wr[4*j+0], acc[p]);
                    acc[p] = fmaf(q.y, wr[4*j+1], acc[p]);
                    acc[p] = fmaf(q.z, wr[4*j+2], acc[p]);
                    acc[p] = fmaf(q.w, wr[4*j+3], acc[p]);
                }
                __syncwarp();   // protect fs before next tap overwrites
            }
        }
    }

    // write conv output (coalesced) + per-warp partial sums for batchnorm
    float s = 0.0f, s2 = 0.0f;
#pragma unroll
    for (int p = 0; p < PW; p++) {
        const float v = acc[p];
        convout[(size_t)(n0 + p) * COUT + lane] = v;
        s  += v;
        s2 += v * v;
    }
    red[0][wid][lane] = s;
    red[1][wid][lane] = s2;
    __syncthreads();
    if (wid == 0) {
        float a = 0.0f, b = 0.0f;
#pragma unroll
        for (int w = 0; w < WARPS1; w++) { a += red[0][w][lane]; b += red[1][w][lane]; }
        partials[(size_t)blockIdx.x * 64 + lane]      = a;
        partials[(size_t)blockIdx.x * 64 + 32 + lane] = b;
    }
}

// ---------------------------------------------------------------------------
// K2: reduce partials -> per-channel scale/shift  (deterministic, single block)
// ---------------------------------------------------------------------------
__global__ __launch_bounds__(1024)
void stats_kernel(const float* __restrict__ part,
                  const float* __restrict__ gamma,
                  const float* __restrict__ beta,
                  float* __restrict__ coef)
{
    const int t = threadIdx.x;
    const int j = t & 63;      // which of 64 stats (sum[32], sumsq[32])
    const int g = t >> 6;      // 16 groups
    float s = 0.0f;
    for (int i = g; i < NBLK1; i += 16) s += part[(size_t)i * 64 + j];
    __shared__ float sm[16][64];
    sm[g][j] = s;
    __syncthreads();
    if (t < 64) {
        float tot = 0.0f;
#pragma unroll
        for (int r = 0; r < 16; r++) tot += sm[r][t];
        sm[0][t] = tot;
    }
    __syncthreads();
    if (t < 32) {
        const float invN  = 1.0f / (float)NPTS;
        const float mean  = sm[0][t] * invN;
        const float ex2   = sm[0][32 + t] * invN;
        const float var   = ex2 - mean * mean;
        const float scale = gamma[t] * rsqrtf(var + 1e-5f);
        coef[t]      = scale;
        coef[32 + t] = beta[t] - mean * scale;
    }
}

// ---------------------------------------------------------------------------
// K3: fused normalize + ReLU (vectorized float4)
// ---------------------------------------------------------------------------
__global__ __launch_bounds__(256)
void norm_kernel(const float* __restrict__ conv,
                 const float* __restrict__ coef,
                 float* __restrict__ out)
{
    const int i = blockIdx.x * 256 + threadIdx.x;   // float4 index
    if (i < TOTAL4) {
        float4 v = ((const float4*)conv)[i];
        const int q = i & 7;   // c_out quad (32 ch = 8 float4s per row)
        const float4 sc = ((const float4*)coef)[q];
        const float4 sh = ((const float4*)(coef + 32))[q];
        v.x = fmaxf(fmaf(v.x, sc.x, sh.x), 0.0f);
        v.y = fmaxf(fmaf(v.y, sc.y, sh.y), 0.0f);
        v.z = fmaxf(fmaf(v.z, sc.z, sh.z), 0.0f);
        v.w = fmaxf(fmaf(v.w, sc.w, sh.w), 0.0f);
        ((float4*)out)[i] = v;
    }
}

// ---------------------------------------------------------------------------
extern "C" void kernel_launch(void* const* d_in, const int* in_sizes, int n_in,
                              void* d_out, int out_size)
{
    const float* feat  = (const float*)d_in[0];
    const float* w     = (const float*)d_in[1];
    const float* gamma = (const float*)d_in[2];
    const float* beta  = (const float*)d_in[3];
    const int*   nidx  = (const int*)d_in[4];
    const void*  nmask = d_in[5];
    float* out = (float*)d_out;

    float* conv;  cudaGetSymbolAddress((void**)&conv,  g_conv);
    float* part;  cudaGetSymbolAddress((void**)&part,  g_part);
    float* coef;  cudaGetSymbolAddress((void**)&coef,  g_coef);

    detect_mask_kernel<<<1, 256>>>((const unsigned int*)nmask);
    conv_kernel<<<NBLK1, BLOCK1>>>(feat, w, nidx,
                                   (const unsigned char*)nmask,
                                   (const int*)nmask,
                                   conv, part);
    stats_kernel<<<1, 1024>>>(part, gamma, beta, coef);
    norm_kernel<<<NBLK3, 256>>>(conv, coef, out);
}

// round 6
// speedup vs baseline: 1.3355x; 1.3355x over previous
#include <cuda_runtime.h>
#include <cuda_bf16.h>

// Problem constants (fixed-shape problem)
#define NPTS   400000
#define CIN    32
#define COUT   32
#define KTAPS  27

#define BLOCK1 256          // 8 warps
#define WARPS1 8
#define PW     16           // points per warp
#define PTSBLK (WARPS1*PW)  // 128 points per block
#define NBLK1  (NPTS/PTSBLK) // 3125 exactly

#define TOTAL4 (NPTS*COUT/4)
#define NBLK3  (TOTAL4/256)

// Scratch (static device memory — no allocations)
__device__ float g_conv[(size_t)NPTS * COUT];
__device__ float g_part[(size_t)NBLK1 * 64];
__device__ float g_coef[64];
__device__ int   g_maskmode;   // 0 = uint8 mask, 1 = int32 mask

// ---------------------------------------------------------------------------
// K0: detect storage width of nbr_mask (int32 {0,1} vs packed uint8 bools)
// ---------------------------------------------------------------------------
__global__ void detect_mask_kernel(const unsigned int* __restrict__ m)
{
    __shared__ int found;
    if (threadIdx.x == 0) found = 0;
    __syncthreads();
    int f = 0;
    for (int i = threadIdx.x; i < 4096; i += blockDim.x)
        if (m[i] > 1u) f = 1;
    if (f) atomicOr(&found, 1);
    __syncthreads();
    if (threadIdx.x == 0) g_maskmode = found ? 0 : 1;
}

// ---------------------------------------------------------------------------
// K1: barrier-free gather-conv.
// lane = c_out; warp owns 16 points. Gathered feature rows are broadcast via
// uniform-address float4 LDGs (L2-resident); weights pulled straight from
// global (L1-cached) per tap. 4-way split dot product for ILP. Zero smem /
// zero barriers in the main loop.
// ---------------------------------------------------------------------------
__global__ __launch_bounds__(BLOCK1)
void conv_kernel(const float* __restrict__ feat,
                 const float* __restrict__ wglob,
                 const int*   __restrict__ nidx,
                 const unsigned char* __restrict__ nmask8,
                 const int*   __restrict__ nmask32,
                 float* __restrict__ convout,
                 float* __restrict__ partials)
{
    __shared__ float red[2][WARPS1][COUT];

    const int tid  = threadIdx.x;
    const int wid  = tid >> 5;
    const int lane = tid & 31;
    const int n0   = blockIdx.x * PTSBLK + wid * PW;
    const int maskmode = g_maskmode;

    float acc[PW];
#pragma unroll
    for (int p = 0; p < PW; p++) acc[p] = 0.0f;

    for (int k = 0; k < KTAPS; k++) {
        // my weight column for this tap: w[k][ci][lane], coalesced, L1-hot
        const float* wk = wglob + k * (CIN * COUT) + lane;
        float wr[CIN];
#pragma unroll
        for (int ci = 0; ci < CIN; ci++) wr[ci] = __ldg(wk + ci * COUT);

        // neighbor idx/mask for this tap (lanes 0..15 carry the 16 points)
        int  idxv = 0;
        bool mv   = false;
        if (lane < PW) {
            const size_t j = (size_t)k * NPTS + (n0 + lane);
            mv   = maskmode ? (nmask32[j] != 0) : (nmask8[j] != 0);
            idxv = nidx[j];
        }
        const unsigned vm = __ballot_sync(0xffffffffu, mv);

#pragma unroll
        for (int p = 0; p < PW; p++) {
            if (vm & (1u << p)) {               // warp-uniform branch
                const int gi = __shfl_sync(0xffffffffu, idxv, p);
                const float4* row = (const float4*)(feat + (size_t)gi * CIN);
                float t0 = 0.f, t1 = 0.f, t2 = 0.f, t3 = 0.f;
#pragma unroll
                for (int j = 0; j < 8; j++) {
                    const float4 q = __ldg(row + j);   // uniform addr: 1 txn, broadcast
                    t0 = fmaf(q.x, wr[4*j+0], t0);
                    t1 = fmaf(q.y, wr[4*j+1], t1);
                    t2 = fmaf(q.z, wr[4*j+2], t2);
                    t3 = fmaf(q.w, wr[4*j+3], t3);
                }
                acc[p] += (t0 + t1) + (t2 + t3);
            }
        }
    }

    // write conv output (coalesced) + per-block partial sums for batchnorm
    float s = 0.0f, s2 = 0.0f;
#pragma unroll
    for (int p = 0; p < PW; p++) {
        const float v = acc[p];
        convout[(size_t)(n0 + p) * COUT + lane] = v;
        s  += v;
        s2 += v * v;
    }
    red[0][wid][lane] = s;
    red[1][wid][lane] = s2;
    __syncthreads();
    if (wid == 0) {
        float a = 0.0f, b = 0.0f;
#pragma unroll
        for (int w = 0; w < WARPS1; w++) { a += red[0][w][lane]; b += red[1][w][lane]; }
        partials[(size_t)blockIdx.x * 64 + lane]      = a;
        partials[(size_t)blockIdx.x * 64 + 32 + lane] = b;
    }
}

// ---------------------------------------------------------------------------
// K2: reduce partials -> per-channel scale/shift (deterministic, single block)
// ---------------------------------------------------------------------------
__global__ __launch_bounds__(1024)
void stats_kernel(const float* __restrict__ part,
                  const float* __restrict__ gamma,
                  const float* __restrict__ beta,
                  float* __restrict__ coef)
{
    const int t = threadIdx.x;
    const int j = t & 63;
    const int g = t >> 6;
    float s = 0.0f;
    for (int i = g; i < NBLK1; i += 16) s += part[(size_t)i * 64 + j];
    __shared__ float sm[16][64];
    sm[g][j] = s;
    __syncthreads();
    if (t < 64) {
        float tot = 0.0f;
#pragma unroll
        for (int r = 0; r < 16; r++) tot += sm[r][t];
        sm[0][t] = tot;
    }
    __syncthreads();
    if (t < 32) {
        const float invN  = 1.0f / (float)NPTS;
        const float mean  = sm[0][t] * invN;
        const float ex2   = sm[0][32 + t] * invN;
        const float var   = ex2 - mean * mean;
        const float scale = gamma[t] * rsqrtf(var + 1e-5f);
        coef[t]      = scale;
        coef[32 + t] = beta[t] - mean * scale;
    }
}

// ---------------------------------------------------------------------------
// K3: fused normalize + ReLU (vectorized float4)
// ---------------------------------------------------------------------------
__global__ __launch_bounds__(256)
void norm_kernel(const float* __restrict__ conv,
                 const float* __restrict__ coef,
                 float* __restrict__ out)
{
    const int i = blockIdx.x * 256 + threadIdx.x;
    if (i < TOTAL4) {
        float4 v = ((const float4*)conv)[i];
        const int q = i & 7;
        const float4 sc = ((const float4*)coef)[q];
        const float4 sh = ((const float4*)(coef + 32))[q];
        v.x = fmaxf(fmaf(v.x, sc.x, sh.x), 0.0f);
        v.y = fmaxf(fmaf(v.y, sc.y, sh.y), 0.0f);
        v.z = fmaxf(fmaf(v.z, sc.z, sh.z), 0.0f);
        v.w = fmaxf(fmaf(v.w, sc.w, sh.w), 0.0f);
        ((float4*)out)[i] = v;
    }
}

// ---------------------------------------------------------------------------
extern "C" void kernel_launch(void* const* d_in, const int* in_sizes, int n_in,
                              void* d_out, int out_size)
{
    const float* feat  = (const float*)d_in[0];
    const float* w     = (const float*)d_in[1];
    const float* gamma = (const float*)d_in[2];
    const float* beta  = (const float*)d_in[3];
    const int*   nidx  = (const int*)d_in[4];
    const void*  nmask = d_in[5];
    float* out = (float*)d_out;

    float* conv;  cudaGetSymbolAddress((void**)&conv,  g_conv);
    float* part;  cudaGetSymbolAddress((void**)&part,  g_part);
    float* coef;  cudaGetSymbolAddress((void**)&coef,  g_coef);

    detect_mask_kernel<<<1, 256>>>((const unsigned int*)nmask);
    conv_kernel<<<NBLK1, BLOCK1>>>(feat, w, nidx,
                                   (const unsigned char*)nmask,
                                   (const int*)nmask,
                                   conv, part);
    stats_kernel<<<1, 1024>>>(part, gamma, beta, coef);
    norm_kernel<<<NBLK3, 256>>>(conv, coef, out);
}

// round 7
// speedup vs baseline: 1.3550x; 1.0146x over previous
#include <cuda_runtime.h>
#include <cuda_bf16.h>

// Problem constants (fixed-shape problem)
#define NPTS   400000
#define CIN    32
#define COUT   32
#define KTAPS  27

#define BLOCK1 128          // 4 warps
#define WARPS1 4
#define PW     32           // points per warp
#define PTSBLK (WARPS1*PW)  // 128 points per block
#define NBLK1  (NPTS/PTSBLK) // 3125 exactly

#define TOTAL4 (NPTS*COUT/4)
#define NBLK3  (TOTAL4/256)

// Scratch (static device memory — no allocations)
__device__ float g_conv[(size_t)NPTS * COUT];
__device__ float g_part[(size_t)NBLK1 * 64];
__device__ float g_coef[64];
__device__ int   g_maskmode;   // 0 = uint8 mask, 1 = int32 mask

// ---------------------------------------------------------------------------
// K0: detect storage width of nbr_mask (int32 {0,1} vs packed uint8 bools)
// ---------------------------------------------------------------------------
__global__ void detect_mask_kernel(const unsigned int* __restrict__ m)
{
    __shared__ int found;
    if (threadIdx.x == 0) found = 0;
    __syncthreads();
    int f = 0;
    for (int i = threadIdx.x; i < 4096; i += blockDim.x)
        if (m[i] > 1u) f = 1;
    if (f) atomicOr(&found, 1);
    __syncthreads();
    if (threadIdx.x == 0) g_maskmode = found ? 0 : 1;
}

// ---------------------------------------------------------------------------
// K1: barrier-free gather-conv, 32 points per warp.
// lane = c_out. Per tap: weight column (32 LDG, L1-hot) amortized over 32
// points; idx/mask prefetched one tap ahead; the 8 row loads of each valid
// tap are explicitly batched (MLP=8) before any FMA consumes them.
// ---------------------------------------------------------------------------
__global__ __launch_bounds__(BLOCK1, 4)
void conv_kernel(const float* __restrict__ feat,
                 const float* __restrict__ wglob,
                 const int*   __restrict__ nidx,
                 const unsigned char* __restrict__ nmask8,
                 const int*   __restrict__ nmask32,
                 float* __restrict__ convout,
                 float* __restrict__ partials)
{
    __shared__ float red[2][WARPS1][COUT];

    const int tid  = threadIdx.x;
    const int wid  = tid >> 5;
    const int lane = tid & 31;
    const int n0   = blockIdx.x * PTSBLK + wid * PW;
    const int maskmode = g_maskmode;

    float acc[PW];
#pragma unroll
    for (int p = 0; p < PW; p++) acc[p] = 0.0f;

    // meta for tap 0 (each lane carries one of the warp's 32 points)
    bool mv;
    int  idxv;
    {
        const size_t j = (size_t)(n0 + lane);
        mv   = maskmode ? (nmask32[j] != 0) : (nmask8[j] != 0);
        idxv = nidx[j];
    }

    for (int k = 0; k < KTAPS; k++) {
        const unsigned vm = __ballot_sync(0xffffffffu, mv);
        const int idxc = idxv;

        // prefetch meta for tap k+1 (hides idx/mask L2 latency behind compute)
        if (k + 1 < KTAPS) {
            const size_t j = (size_t)(k + 1) * NPTS + (n0 + lane);
            mv   = maskmode ? (nmask32[j] != 0) : (nmask8[j] != 0);
            idxv = nidx[j];
        }

        // weight column for this tap: w[k][ci][lane] (coalesced, L1-hot)
        const float* wk = wglob + k * (CIN * COUT) + lane;
        float wr[CIN];
#pragma unroll
        for (int ci = 0; ci < CIN; ci++) wr[ci] = __ldg(wk + ci * COUT);

#pragma unroll
        for (int p = 0; p < PW; p++) {
            if (vm & (1u << p)) {               // warp-uniform branch
                const int gi = __shfl_sync(0xffffffffu, idxc, p);
                const float4* row = (const float4*)(feat + (size_t)gi * CIN);
                // batch all 8 uniform-address loads (MLP=8, one latency exposure)
                const float4 q0 = __ldg(row + 0);
                const float4 q1 = __ldg(row + 1);
                const float4 q2 = __ldg(row + 2);
                const float4 q3 = __ldg(row + 3);
                const float4 q4 = __ldg(row + 4);
                const float4 q5 = __ldg(row + 5);
                const float4 q6 = __ldg(row + 6);
                const float4 q7 = __ldg(row + 7);
                float t0 = 0.f, t1 = 0.f, t2 = 0.f, t3 = 0.f;
                t0 = fmaf(q0.x, wr[ 0], t0); t1 = fmaf(q0.y, wr[ 1], t1);
                t2 = fmaf(q0.z, wr[ 2], t2); t3 = fmaf(q0.w, wr[ 3], t3);
                t0 = fmaf(q1.x, wr[ 4], t0); t1 = fmaf(q1.y, wr[ 5], t1);
                t2 = fmaf(q1.z, wr[ 6], t2); t3 = fmaf(q1.w, wr[ 7], t3);
                t0 = fmaf(q2.x, wr[ 8], t0); t1 = fmaf(q2.y, wr[ 9], t1);
                t2 = fmaf(q2.z, wr[10], t2); t3 = fmaf(q2.w, wr[11], t3);
                t0 = fmaf(q3.x, wr[12], t0); t1 = fmaf(q3.y, wr[13], t1);
                t2 = fmaf(q3.z, wr[14], t2); t3 = fmaf(q3.w, wr[15], t3);
                t0 = fmaf(q4.x, wr[16], t0); t1 = fmaf(q4.y, wr[17], t1);
                t2 = fmaf(q4.z, wr[18], t2); t3 = fmaf(q4.w, wr[19], t3);
                t0 = fmaf(q5.x, wr[20], t0); t1 = fmaf(q5.y, wr[21], t1);
                t2 = fmaf(q5.z, wr[22], t2); t3 = fmaf(q5.w, wr[23], t3);
                t0 = fmaf(q6.x, wr[24], t0); t1 = fmaf(q6.y, wr[25], t1);
                t2 = fmaf(q6.z, wr[26], t2); t3 = fmaf(q6.w, wr[27], t3);
                t0 = fmaf(q7.x, wr[28], t0); t1 = fmaf(q7.y, wr[29], t1);
                t2 = fmaf(q7.z, wr[30], t2); t3 = fmaf(q7.w, wr[31], t3);
                acc[p] += (t0 + t1) + (t2 + t3);
            }
        }
    }

    // write conv output (coalesced) + per-block partial sums for batchnorm
    float s = 0.0f, s2 = 0.0f;
#pragma unroll
    for (int p = 0; p < PW; p++) {
        const float v = acc[p];
        convout[(size_t)(n0 + p) * COUT + lane] = v;
        s  += v;
        s2 += v * v;
    }
    red[0][wid][lane] = s;
    red[1][wid][lane] = s2;
    __syncthreads();
    if (wid == 0) {
        float a = 0.0f, b = 0.0f;
#pragma unroll
        for (int w = 0; w < WARPS1; w++) { a += red[0][w][lane]; b += red[1][w][lane]; }
        partials[(size_t)blockIdx.x * 64 + lane]      = a;
        partials[(size_t)blockIdx.x * 64 + 32 + lane] = b;
    }
}

// ---------------------------------------------------------------------------
// K2: reduce partials -> per-channel scale/shift (deterministic, single block)
// ---------------------------------------------------------------------------
__global__ __launch_bounds__(1024)
void stats_kernel(const float* __restrict__ part,
                  const float* __restrict__ gamma,
                  const float* __restrict__ beta,
                  float* __restrict__ coef)
{
    const int t = threadIdx.x;
    const int j = t & 63;
    const int g = t >> 6;
    float s = 0.0f;
    for (int i = g; i < NBLK1; i += 16) s += part[(size_t)i * 64 + j];
    __shared__ float sm[16][64];
    sm[g][j] = s;
    __syncthreads();
    if (t < 64) {
        float tot = 0.0f;
#pragma unroll
        for (int r = 0; r < 16; r++) tot += sm[r][t];
        sm[0][t] = tot;
    }
    __syncthreads();
    if (t < 32) {
        const float invN  = 1.0f / (float)NPTS;
        const float mean  = sm[0][t] * invN;
        const float ex2   = sm[0][32 + t] * invN;
        const float var   = ex2 - mean * mean;
        const float scale = gamma[t] * rsqrtf(var + 1e-5f);
        coef[t]      = scale;
        coef[32 + t] = beta[t] - mean * scale;
    }
}

// ---------------------------------------------------------------------------
// K3: fused normalize + ReLU (vectorized float4)
// ---------------------------------------------------------------------------
__global__ __launch_bounds__(256)
void norm_kernel(const float* __restrict__ conv,
                 const float* __restrict__ coef,
                 float* __restrict__ out)
{
    const int i = blockIdx.x * 256 + threadIdx.x;
    if (i < TOTAL4) {
        float4 v = ((const float4*)conv)[i];
        const int q = i & 7;
        const float4 sc = ((const float4*)coef)[q];
        const float4 sh = ((const float4*)(coef + 32))[q];
        v.x = fmaxf(fmaf(v.x, sc.x, sh.x), 0.0f);
        v.y = fmaxf(fmaf(v.y, sc.y, sh.y), 0.0f);
        v.z = fmaxf(fmaf(v.z, sc.z, sh.z), 0.0f);
        v.w = fmaxf(fmaf(v.w, sc.w, sh.w), 0.0f);
        ((float4*)out)[i] = v;
    }
}

// ---------------------------------------------------------------------------
extern "C" void kernel_launch(void* const* d_in, const int* in_sizes, int n_in,
                              void* d_out, int out_size)
{
    const float* feat  = (const float*)d_in[0];
    const float* w     = (const float*)d_in[1];
    const float* gamma = (const float*)d_in[2];
    const float* beta  = (const float*)d_in[3];
    const int*   nidx  = (const int*)d_in[4];
    const void*  nmask = d_in[5];
    float* out = (float*)d_out;

    float* conv;  cudaGetSymbolAddress((void**)&conv,  g_conv);
    float* part;  cudaGetSymbolAddress((void**)&part,  g_part);
    float* coef;  cudaGetSymbolAddress((void**)&coef,  g_coef);

    detect_mask_kernel<<<1, 256>>>((const unsigned int*)nmask);
    conv_kernel<<<NBLK1, BLOCK1>>>(feat, w, nidx,
                                   (const unsigned char*)nmask,
                                   (const int*)nmask,
                                   conv, part);
    stats_kernel<<<1, 1024>>>(part, gamma, beta, coef);
    norm_kernel<<<NBLK3, 256>>>(conv, coef, out);
}

// round 9
// speedup vs baseline: 1.9664x; 1.4512x over previous
#include <cuda_runtime.h>
#include <cuda_bf16.h>

// Problem constants (fixed-shape problem)
#define NPTS   400000
#define CIN    32
#define COUT   32
#define KTAPS  27

#define BLOCK1 128          // 4 warps
#define WARPS1 4
#define PW     32           // points per warp
#define PTSBLK (WARPS1*PW)  // 128 points per block
#define NBLK1  (NPTS/PTSBLK) // 3125 exactly

#define TOTAL4 (NPTS*COUT/4)
#define NBLK3  (TOTAL4/256)

// Scratch (static device memory — no allocations)
__device__ float g_conv[(size_t)NPTS * COUT];
__device__ float g_part[(size_t)NBLK1 * 64];
__device__ float g_coef[64];
__device__ int   g_maskmode;   // 0 = uint8 mask, 1 = int32 mask

// ---------------------------------------------------------------------------
// K0: detect storage width of nbr_mask (int32 {0,1} vs packed uint8 bools)
// ---------------------------------------------------------------------------
__global__ void detect_mask_kernel(const unsigned int* __restrict__ m)
{
    __shared__ int found;
    if (threadIdx.x == 0) found = 0;
    __syncthreads();
    int f = 0;
    for (int i = threadIdx.x; i < 4096; i += blockDim.x)
        if (m[i] > 1u) f = 1;
    if (f) atomicOr(&found, 1);
    __syncthreads();
    if (threadIdx.x == 0) g_maskmode = found ? 0 : 1;
}

// ---------------------------------------------------------------------------
// K1: branch-free-inner gather-conv.
// lane = c_out; warp owns 32 points. Per tap k: one coalesced meta load +
// ballot; then a tight set-bit iteration over VALID taps only (one uniform
// taken-branch per valid tap, no BSSY-per-point). Accumulators live in a
// per-thread-exclusive smem array (dynamic point index), conflict-free,
// no synchronization needed.
// ---------------------------------------------------------------------------
__global__ __launch_bounds__(BLOCK1)
void conv_kernel(const float* __restrict__ feat,
                 const float* __restrict__ wglob,
                 const int*   __restrict__ nidx,
                 const unsigned char* __restrict__ nmask8,
                 const int*   __restrict__ nmask32,
                 float* __restrict__ convout,
                 float* __restrict__ partials)
{
    // sacc[point_in_block][lane] : each thread exclusively owns column `lane`
    // of its warp's 32 rows. 128*32*4 = 16 KB.
    __shared__ float sacc[PTSBLK * 32];
    __shared__ float red[2][WARPS1][COUT];

    const int tid  = threadIdx.x;
    const int wid  = tid >> 5;
    const int lane = tid & 31;
    const int n0   = blockIdx.x * PTSBLK + wid * PW;
    const int maskmode = g_maskmode;

    // zero my 32 accumulator slots (rows wid*32..wid*32+31, column lane)
#pragma unroll
    for (int p = 0; p < PW; p++) sacc[(wid * PW + p) * 32 + lane] = 0.0f;

    // meta for tap 0 (each lane carries one of the warp's 32 points)
    bool mv;
    int  idxv;
    {
        const size_t j = (size_t)(n0 + lane);
        mv   = maskmode ? (nmask32[j] != 0) : (nmask8[j] != 0);
        idxv = nidx[j];
    }

    for (int k = 0; k < KTAPS; k++) {
        const unsigned vm = __ballot_sync(0xffffffffu, mv);
        const int idxc = idxv;

        // prefetch meta for tap k+1
        if (k + 1 < KTAPS) {
            const size_t j = (size_t)(k + 1) * NPTS + (n0 + lane);
            mv   = maskmode ? (nmask32[j] != 0) : (nmask8[j] != 0);
            idxv = nidx[j];
        }

        if (vm == 0u) continue;   // warp-uniform; ~4% of taps

        // weight column for this tap: w[k][ci][lane] (coalesced, L1-hot)
        const float* wk = wglob + k * (CIN * COUT) + lane;
        float wr[CIN];
#pragma unroll
        for (int ci = 0; ci < CIN; ci++) wr[ci] = __ldg(wk + ci * COUT);

        // iterate set bits only: one uniform taken-branch per VALID tap
        unsigned rem = vm;
        while (rem) {
            const int p = __ffs(rem) - 1;
            rem &= rem - 1u;
            const int gi = __shfl_sync(0xffffffffu, idxc, p);
            const float4* row = (const float4*)(feat + (size_t)gi * CIN);
            // batch all 8 uniform-address loads (1 txn each, broadcast)
            const float4 q0 = __ldg(row + 0);
            const float4 q1 = __ldg(row + 1);
            const float4 q2 = __ldg(row + 2);
            const float4 q3 = __ldg(row + 3);
            const float4 q4 = __ldg(row + 4);
            const float4 q5 = __ldg(row + 5);
            const float4 q6 = __ldg(row + 6);
            const float4 q7 = __ldg(row + 7);
            float t0 = 0.f, t1 = 0.f, t2 = 0.f, t3 = 0.f;
            t0 = fmaf(q0.x, wr[ 0], t0); t1 = fmaf(q0.y, wr[ 1], t1);
            t2 = fmaf(q0.z, wr[ 2], t2); t3 = fmaf(q0.w, wr[ 3], t3);
            t0 = fmaf(q1.x, wr[ 4], t0); t1 = fmaf(q1.y, wr[ 5], t1);
            t2 = fmaf(q1.z, wr[ 6], t2); t3 = fmaf(q1.w, wr[ 7], t3);
            t0 = fmaf(q2.x, wr[ 8], t0); t1 = fmaf(q2.y, wr[ 9], t1);
            t2 = fmaf(q2.z, wr[10], t2); t3 = fmaf(q2.w, wr[11], t3);
            t0 = fmaf(q3.x, wr[12], t0); t1 = fmaf(q3.y, wr[13], t1);
            t2 = fmaf(q3.z, wr[14], t2); t3 = fmaf(q3.w, wr[15], t3);
            t0 = fmaf(q4.x, wr[16], t0); t1 = fmaf(q4.y, wr[17], t1);
            t2 = fmaf(q4.z, wr[18], t2); t3 = fmaf(q4.w, wr[19], t3);
            t0 = fmaf(q5.x, wr[20], t0); t1 = fmaf(q5.y, wr[21], t1);
            t2 = fmaf(q5.z, wr[22], t2); t3 = fmaf(q5.w, wr[23], t3);
            t0 = fmaf(q6.x, wr[24], t0); t1 = fmaf(q6.y, wr[25], t1);
            t2 = fmaf(q6.z, wr[26], t2); t3 = fmaf(q6.w, wr[27], t3);
            t0 = fmaf(q7.x, wr[28], t0); t1 = fmaf(q7.y, wr[29], t1);
            t2 = fmaf(q7.z, wr[30], t2); t3 = fmaf(q7.w, wr[31], t3);
            const float dot = (t0 + t1) + (t2 + t3);
            // exclusive slot: same thread RMW, in program order — no sync
            sacc[(wid * PW + p) * 32 + lane] += dot;
        }
    }

    // write conv output (coalesced) + per-block partial sums for batchnorm
    float s = 0.0f, s2 = 0.0f;
#pragma unroll
    for (int p = 0; p < PW; p++) {
        const float v = sacc[(wid * PW + p) * 32 + lane];
        convout[(size_t)(n0 + p) * COUT + lane] = v;
        s  += v;
        s2 += v * v;
    }
    red[0][wid][lane] = s;
    red[1][wid][lane] = s2;
    __syncthreads();
    if (wid == 0) {
        float a = 0.0f, b = 0.0f;
#pragma unroll
        for (int w = 0; w < WARPS1; w++) { a += red[0][w][lane]; b += red[1][w][lane]; }
        partials[(size_t)blockIdx.x * 64 + lane]      = a;
        partials[(size_t)blockIdx.x * 64 + 32 + lane] = b;
    }
}

// ---------------------------------------------------------------------------
// K2: reduce partials -> per-channel scale/shift (deterministic, single block)
// ---------------------------------------------------------------------------
__global__ __launch_bounds__(1024)
void stats_kernel(const float* __restrict__ part,
                  const float* __restrict__ gamma,
                  const float* __restrict__ beta,
                  float* __restrict__ coef)
{
    const int t = threadIdx.x;
    const int j = t & 63;
    const int g = t >> 6;
    float s = 0.0f;
    for (int i = g; i < NBLK1; i += 16) s += part[(size_t)i * 64 + j];
    __shared__ float sm[16][64];
    sm[g][j] = s;
    __syncthreads();
    if (t < 64) {
        float tot = 0.0f;
#pragma unroll
        for (int r = 0; r < 16; r++) tot += sm[r][t];
        sm[0][t] = tot;
    }
    __syncthreads();
    if (t < 32) {
        const float invN  = 1.0f / (float)NPTS;
        const float mean  = sm[0][t] * invN;
        const float ex2   = sm[0][32 + t] * invN;
        const float var   = ex2 - mean * mean;
        const float scale = gamma[t] * rsqrtf(var + 1e-5f);
        coef[t]      = scale;
        coef[32 + t] = beta[t] - mean * scale;
    }
}

// ---------------------------------------------------------------------------
// K3: fused normalize + ReLU (vectorized float4)
// ---------------------------------------------------------------------------
__global__ __launch_bounds__(256)
void norm_kernel(const float* __restrict__ conv,
                 const float* __restrict__ coef,
                 float* __restrict__ out)
{
    const int i = blockIdx.x * 256 + threadIdx.x;
    if (i < TOTAL4) {
        float4 v = ((const float4*)conv)[i];
        const int q = i & 7;
        const float4 sc = ((const float4*)coef)[q];
        const float4 sh = ((const float4*)(coef + 32))[q];
        v.x = fmaxf(fmaf(v.x, sc.x, sh.x), 0.0f);
        v.y = fmaxf(fmaf(v.y, sc.y, sh.y), 0.0f);
        v.z = fmaxf(fmaf(v.z, sc.z, sh.z), 0.0f);
        v.w = fmaxf(fmaf(v.w, sc.w, sh.w), 0.0f);
        ((float4*)out)[i] = v;
    }
}

// ---------------------------------------------------------------------------
extern "C" void kernel_launch(void* const* d_in, const int* in_sizes, int n_in,
                              void* d_out, int out_size)
{
    const float* feat  = (const float*)d_in[0];
    const float* w     = (const float*)d_in[1];
    const float* gamma = (const float*)d_in[2];
    const float* beta  = (const float*)d_in[3];
    const int*   nidx  = (const int*)d_in[4];
    const void*  nmask = d_in[5];
    float* out = (float*)d_out;

    float* conv;  cudaGetSymbolAddress((void**)&conv,  g_conv);
    float* part;  cudaGetSymbolAddress((void**)&part,  g_part);
    float* coef;  cudaGetSymbolAddress((void**)&coef,  g_coef);

    detect_mask_kernel<<<1, 256>>>((const unsigned int*)nmask);
    conv_kernel<<<NBLK1, BLOCK1>>>(feat, w, nidx,
                                   (const unsigned char*)nmask,
                                   (const int*)nmask,
                                   conv, part);
    stats_kernel<<<1, 1024>>>(part, gamma, beta, coef);
    norm_kernel<<<NBLK3, 256>>>(conv, coef, out);
}